// round 12
// baseline (speedup 1.0000x reference)
#include <cuda_runtime.h>
#include <cstdint>

#define BB 2
#define HH 8
#define LL 512
#define DD 64
#define TEMPINV 0.125f

#define OUT_ELEMS  (BB*HH*LL*DD)
#define ATTN_ELEMS (BB*HH*LL*LL)

// 16 MB scratch for base scores qs@k^T ; 16 MB fallback attn buffer
__device__ float g_s0[ATTN_ELEMS];
__device__ float g_attn_fb[ATTN_ELEMS];

// ---------- PTX helpers ----------
__device__ __forceinline__ void cpa16(uint32_t dst, const void* src) {
    asm volatile("cp.async.cg.shared.global [%0], [%1], 16;" :: "r"(dst), "l"(src) : "memory");
}
#define CP_COMMIT asm volatile("cp.async.commit_group;" ::: "memory")
#define CP_WAIT1  asm volatile("cp.async.wait_group 1;" ::: "memory")
#define CP_WAIT0  asm volatile("cp.async.wait_group 0;" ::: "memory")

__device__ __forceinline__ void fma2(unsigned long long& d,
                                     unsigned long long a, unsigned long long b) {
    asm("fma.rn.f32x2 %0, %1, %2, %0;" : "+l"(d) : "l"(a), "l"(b));
}
__device__ __forceinline__ float hadd2(unsigned long long v) {
    float lo, hi;
    asm("mov.b64 {%0,%1}, %2;" : "=f"(lo), "=f"(hi) : "l"(v));
    return lo + hi;
}
__device__ __forceinline__ unsigned long long pack2(float lo, float hi) {
    unsigned long long r;
    asm("mov.b64 %0, {%1,%2};" : "=l"(r) : "f"(lo), "f"(hi));
    return r;
}
__device__ __forceinline__ void unpack2(float& lo, float& hi, unsigned long long v) {
    asm("mov.b64 {%0,%1}, %2;" : "=f"(lo), "=f"(hi) : "l"(v));
}
__device__ __forceinline__ float warp_max(float x) {
#pragma unroll
    for (int o = 16; o; o >>= 1) x = fmaxf(x, __shfl_xor_sync(0xffffffffu, x, o));
    return x;
}
__device__ __forceinline__ float warp_sum(float x) {
#pragma unroll
    for (int o = 16; o; o >>= 1) x += __shfl_xor_sync(0xffffffffu, x, o);
    return x;
}

// =====================================================================
// Kernel 1: QK base scores. g_s0[bh,i,j] = (q/8)[bh,i,:] . k[bh,j,:]
// (exact R6 version — 20.5us measured)
// =====================================================================
#define QK_PADI 132
#define QK_SMEM_FLOATS (2*64*QK_PADI)   // 16896 -> 67584 B

__global__ void __launch_bounds__(256, 2)
qk_kernel(const float* __restrict__ q, const float* __restrict__ k)
{
    extern __shared__ float smq[];
    float* qT = smq;                 // [64 d][132]
    float* kT = smq + 64 * QK_PADI;  // [64 d][132]
    const int bid = blockIdx.x;
    const int bh = bid >> 4;
    const int it = (bid >> 2) & 3, jt = bid & 3;
    const int i0 = it * 128, j0 = jt * 128;
    const int tid = threadIdx.x;

    const float* qb = q + ((size_t)bh * LL + i0) * DD;
    const float* kb = k + ((size_t)bh * LL + j0) * DD;
#pragma unroll
    for (int f = tid; f < 128 * 64; f += 256) {
        int i = f >> 6, d = f & 63;
        qT[d * QK_PADI + i] = qb[(size_t)i * DD + d] * TEMPINV;
        kT[d * QK_PADI + i] = kb[(size_t)i * DD + d];
    }
    __syncthreads();

    const int ty = tid >> 4, tx = tid & 15;
    const int il = ty * 8, jl = tx * 8;
    unsigned long long acc[8][4];
#pragma unroll
    for (int r = 0; r < 8; r++)
#pragma unroll
        for (int c = 0; c < 4; c++) acc[r][c] = 0ull;

#pragma unroll 4
    for (int d = 0; d < 64; d++) {
        float4 a0 = *reinterpret_cast<const float4*>(qT + d * QK_PADI + il);
        float4 a1 = *reinterpret_cast<const float4*>(qT + d * QK_PADI + il + 4);
        const ulonglong2* bp = reinterpret_cast<const ulonglong2*>(kT + d * QK_PADI + jl);
        ulonglong2 b01 = bp[0], b23 = bp[1];
        float a[8] = {a0.x,a0.y,a0.z,a0.w,a1.x,a1.y,a1.z,a1.w};
#pragma unroll
        for (int r = 0; r < 8; r++) {
            unsigned long long ar = pack2(a[r], a[r]);
            fma2(acc[r][0], ar, b01.x);
            fma2(acc[r][1], ar, b01.y);
            fma2(acc[r][2], ar, b23.x);
            fma2(acc[r][3], ar, b23.y);
        }
    }

#pragma unroll
    for (int r = 0; r < 8; r++) {
        float c[8];
#pragma unroll
        for (int c2 = 0; c2 < 4; c2++) unpack2(c[2*c2], c[2*c2+1], acc[r][c2]);
        float* dst = g_s0 + ((size_t)bh * LL + i0 + il + r) * LL + j0 + jl;
        float4 v0 = {c[0], c[1], c[2], c[3]};
        float4 v1 = {c[4], c[5], c[6], c[7]};
        *reinterpret_cast<float4*>(dst)     = v0;
        *reinterpret_cast<float4*>(dst + 4) = v1;
    }
}

// =====================================================================
// Kernel 2 (p1): adj-score accumulation + softmax -> attn
// grid 256 = (b, i-tile of 4 rows), 256 thr, 2 CTAs/SM (all resident)
// warp = (ti, hg): 4 rows h0..h0+3, lanes = 32 j, 16 tiles of 32 j
// Softmax fully warp-local.
// =====================================================================
#define P1_TI 4
#define P1_NT 256
#define P1_QS 0                    // qs[4][8][64] = 2048
#define P1_MK 2048                 // 512
#define P1_BUF 2560                // double buffers
#define P1_TILE (4*32*68)          // 8704 floats
#define P1_SMEM_FLOATS (P1_BUF + 2*P1_TILE)   // 19968 -> 79872 B

__global__ void __launch_bounds__(P1_NT, 2)
p1_kernel(const float* __restrict__ q, const float* __restrict__ adjk,
          const int* __restrict__ mask,
          float* __restrict__ attn_ext, int write_ext)
{
    extern __shared__ float sm[];
    float* attn = write_ext ? attn_ext : g_attn_fb;

    const int bid  = blockIdx.x;
    const int b    = bid >> 7;               // 128 i-tiles per batch
    const int i0   = (bid & 127) * P1_TI;
    const int tid  = threadIdx.x;
    const int w    = tid >> 5;
    const int lane = tid & 31;

    float* qs = sm + P1_QS;
    float* mk = sm + P1_MK;
    const uint32_t smemU = (uint32_t)__cvta_generic_to_shared(sm);

    // ---- qs (scaled q) + mask flags ----
    {
        int d4 = tid & 15, h = (tid >> 4) & 7, ti = tid >> 7;
        // 256 threads cover ti 0..1; second half via +2 offset
#pragma unroll
        for (int tt = 0; tt < 2; tt++) {
            int tii = ti + tt * 2;
            float4 val = *reinterpret_cast<const float4*>(
                &q[((size_t)(b * HH + h) * LL + i0 + tii) * DD + d4 * 4]);
            val.x *= TEMPINV; val.y *= TEMPINV; val.z *= TEMPINV; val.w *= TEMPINV;
            reinterpret_cast<float4*>(qs)[(tii * HH + h) * (DD / 4) + d4] = val;
        }
        mk[tid]       = (mask[b * LL + tid]       != 0) ? 1.0f : 0.0f;
        mk[tid + 256] = (mask[b * LL + tid + 256] != 0) ? 1.0f : 0.0f;
    }

    // warp mapping: ti = w>>1, hg = w&1, rows h0..h0+3
    const int ti = w >> 1;
    const int h0 = (w & 1) * 4;
    const int jj = lane;
    const int rbase = ti * HH + h0;

    const float* adjk_b = adjk + ((size_t)(b * LL + i0) * LL) * DD;

    // prologue: stage tile 0 (4 ti x 32 j x 64 d -> pad 68)
    {
#pragma unroll
        for (int s2 = 0; s2 < 8; s2++) {
            int f = tid + s2 * P1_NT;
            int d4 = f & 15, row = f >> 4;        // row 0..127
            int jjx = row & 31, ti2 = row >> 5;
            cpa16(smemU + (uint32_t)(P1_BUF + (ti2 * 32 + jjx) * 68 + d4 * 4) * 4,
                  adjk_b + (size_t)ti2 * (LL * DD) + (size_t)jjx * DD + d4 * 4);
        }
        CP_COMMIT;
    }

    // init scores from g_s0 : s[hh][t], hh = row within group, t = tile
    float s[4][16];
#pragma unroll
    for (int hh = 0; hh < 4; hh++) {
        const float* srow = g_s0 + ((size_t)(b * HH + h0 + hh) * LL + i0 + ti) * LL;
#pragma unroll
        for (int t = 0; t < 16; t++)
            s[hh][t] = srow[t * 32 + jj];
    }

    const ulonglong2* q0p = reinterpret_cast<const ulonglong2*>(qs + (rbase + 0) * DD);
    const ulonglong2* q1p = reinterpret_cast<const ulonglong2*>(qs + (rbase + 1) * DD);
    const ulonglong2* q2p = reinterpret_cast<const ulonglong2*>(qs + (rbase + 2) * DD);
    const ulonglong2* q3p = reinterpret_cast<const ulonglong2*>(qs + (rbase + 3) * DD);

    // ---- 16 tiles of 32 j, double-buffered ----
#pragma unroll 1
    for (int t = 0; t < 16; t++) {
        if (t < 15) {
            const float* srcb = adjk_b + (size_t)(t + 1) * 32 * DD;
            const int base = P1_BUF + ((t + 1) & 1) * P1_TILE;
#pragma unroll
            for (int s2 = 0; s2 < 8; s2++) {
                int f = tid + s2 * P1_NT;
                int d4 = f & 15, row = f >> 4;
                int jjx = row & 31, ti2 = row >> 5;
                cpa16(smemU + (uint32_t)(base + (ti2 * 32 + jjx) * 68 + d4 * 4) * 4,
                      srcb + (size_t)ti2 * (LL * DD) + (size_t)jjx * DD + d4 * 4);
            }
            CP_COMMIT;
            CP_WAIT1;
        } else {
            CP_WAIT0;
        }
        __syncthreads();

        const float* bufp = sm + P1_BUF + (t & 1) * P1_TILE;
        const ulonglong2* ap = reinterpret_cast<const ulonglong2*>(bufp + (ti * 32 + jj) * 68);
        unsigned long long a0 = 0ull, a1 = 0ull, a2 = 0ull, a3 = 0ull;
#pragma unroll
        for (int d4 = 0; d4 < 16; d4++) {
            ulonglong2 ad = ap[d4];
            ulonglong2 v0 = q0p[d4]; fma2(a0, v0.x, ad.x); fma2(a0, v0.y, ad.y);
            ulonglong2 v1 = q1p[d4]; fma2(a1, v1.x, ad.x); fma2(a1, v1.y, ad.y);
            ulonglong2 v2 = q2p[d4]; fma2(a2, v2.x, ad.x); fma2(a2, v2.y, ad.y);
            ulonglong2 v3 = q3p[d4]; fma2(a3, v3.x, ad.x); fma2(a3, v3.y, ad.y);
        }
        s[0][t] += hadd2(a0); s[1][t] += hadd2(a1);
        s[2][t] += hadd2(a2); s[3][t] += hadd2(a3);
        __syncthreads();
    }

    // ---- warp-local softmax over this warp's 4 rows (all 512 j visible) ----
    float m[4] = {-3.4e38f, -3.4e38f, -3.4e38f, -3.4e38f};
#pragma unroll
    for (int t = 0; t < 16; t++) {
        bool live = mk[t * 32 + jj] != 0.0f;
#pragma unroll
        for (int hh = 0; hh < 4; hh++) {
            float x = live ? s[hh][t] : -10000.0f;
            s[hh][t] = x;
            m[hh] = fmaxf(m[hh], x);
        }
    }
#pragma unroll
    for (int hh = 0; hh < 4; hh++) m[hh] = warp_max(m[hh]);

    float sum[4] = {0.f, 0.f, 0.f, 0.f};
#pragma unroll
    for (int t = 0; t < 16; t++)
#pragma unroll
        for (int hh = 0; hh < 4; hh++) {
            float e = __expf(s[hh][t] - m[hh]);
            s[hh][t] = e;
            sum[hh] += e;
        }
#pragma unroll
    for (int hh = 0; hh < 4; hh++) sum[hh] = 1.0f / warp_sum(sum[hh]);

#pragma unroll
    for (int hh = 0; hh < 4; hh++) {
        float* arow = attn + ((size_t)(b * HH + h0 + hh) * LL + i0 + ti) * LL;
#pragma unroll
        for (int t = 0; t < 16; t++)
            arow[t * 32 + jj] = s[hh][t] * sum[hh];
    }
}

// =====================================================================
// Kernel 3 (adjv): out[b,h,i,:] = sum_j p[b,h,i,j] * adjv[b,i,j,:]
// grid 1024 = (b, i), 256 thr = 8 warps (each warp: 64 j), smem reduce
// =====================================================================
__global__ void __launch_bounds__(256, 4)
adjv_kernel(const float* __restrict__ adjv, float* __restrict__ out,
            const float* __restrict__ attn_ext, int write_ext)
{
    __shared__ float red[8 * 8 * 64];   // [warp][h][d] = 16 KB
    const float* attn = write_ext ? attn_ext : g_attn_fb;

    const int bid  = blockIdx.x;
    const int b    = bid >> 9;
    const int i    = bid & 511;
    const int tid  = threadIdx.x;
    const int w    = tid >> 5;
    const int lane = tid & 31;
    const int l2   = lane * 2;

    const float* avb = adjv + ((size_t)(b * LL + i) * LL) * DD;
    const float* pr[8];
#pragma unroll
    for (int h = 0; h < 8; h++)
        pr[h] = attn + ((size_t)(b * HH + h) * LL + i) * LL;

    float2 acc[8];
#pragma unroll
    for (int h = 0; h < 8; h++) { acc[h].x = 0.f; acc[h].y = 0.f; }

    const int j0w = w * 64;
#pragma unroll 4
    for (int jj = 0; jj < 64; jj += 2) {
        const int j = j0w + jj;
        float2 p[8];
#pragma unroll
        for (int h = 0; h < 8; h++)
            p[h] = *reinterpret_cast<const float2*>(pr[h] + j);   // warp-uniform
        float2 av0 = *reinterpret_cast<const float2*>(avb + (size_t)(j + 0) * DD + l2);
        float2 av1 = *reinterpret_cast<const float2*>(avb + (size_t)(j + 1) * DD + l2);
#pragma unroll
        for (int h = 0; h < 8; h++) {
            acc[h].x += p[h].x * av0.x + p[h].y * av1.x;
            acc[h].y += p[h].x * av0.y + p[h].y * av1.y;
        }
    }

#pragma unroll
    for (int h = 0; h < 8; h++)
        *reinterpret_cast<float2*>(red + (w * 8 + h) * 64 + l2) = acc[h];
    __syncthreads();

    // reduce across 8 warps: 512 outputs, 2 per thread
#pragma unroll
    for (int o = tid; o < 512; o += 256) {
        int h = o >> 6, d = o & 63;
        float v = 0.f;
#pragma unroll
        for (int ww = 0; ww < 8; ww++)
            v += red[(ww * 8 + h) * 64 + d];
        out[((size_t)(b * HH + h) * LL + i) * DD + d] = v;
    }
}

// =====================================================================
// Kernel 4: out += attn @ v.  (exact R6 version)
// =====================================================================
__global__ void __launch_bounds__(256, 4)
av_kernel(const float* __restrict__ v, float* __restrict__ out,
          const float* __restrict__ attn_ext, int write_ext)
{
    __shared__ float aS[2][32 * 32];   // [i][j]
    __shared__ float vS[2][32 * 64];   // [j][d]
    const float* attn = write_ext ? attn_ext : g_attn_fb;

    const int bid = blockIdx.x;
    const int bh  = bid >> 4;
    const int i0  = (bid & 15) * 32;
    const int tid = threadIdx.x;
    const uint32_t aU = (uint32_t)__cvta_generic_to_shared(&aS[0][0]);
    const uint32_t vU = (uint32_t)__cvta_generic_to_shared(&vS[0][0]);

    const float* ab = attn + ((size_t)bh * LL + i0) * LL;
    const float* vb = v + (size_t)bh * LL * DD;

    // stage tile 0
    {
        int i = tid >> 3, c = tid & 7;
        cpa16(aU + (uint32_t)(i * 32 + c * 4) * 4, ab + (size_t)i * LL + c * 4);
#pragma unroll
        for (int s2 = 0; s2 < 2; s2++) {
            int f = tid + s2 * 256;
            int j = f >> 4, d4 = f & 15;
            cpa16(vU + (uint32_t)(j * 64 + d4 * 4) * 4, vb + (size_t)j * DD + d4 * 4);
        }
        CP_COMMIT;
    }

    const int ty = tid >> 5, tx = tid & 31;
    float2 o[4];
#pragma unroll
    for (int r = 0; r < 4; r++) { o[r].x = 0.f; o[r].y = 0.f; }

#pragma unroll 1
    for (int kt = 0; kt < 16; kt++) {
        if (kt < 15) {
            int j0 = (kt + 1) * 32;
            int bsel = (kt + 1) & 1;
            int i = tid >> 3, c = tid & 7;
            cpa16(aU + (uint32_t)(bsel * 1024 + i * 32 + c * 4) * 4,
                  ab + (size_t)i * LL + j0 + c * 4);
#pragma unroll
            for (int s2 = 0; s2 < 2; s2++) {
                int f = tid + s2 * 256;
                int j = f >> 4, d4 = f & 15;
                cpa16(vU + (uint32_t)(bsel * 2048 + j * 64 + d4 * 4) * 4,
                      vb + (size_t)(j0 + j) * DD + d4 * 4);
            }
            CP_COMMIT;
            CP_WAIT1;
        } else {
            CP_WAIT0;
        }
        __syncthreads();

        const float* aT = &aS[kt & 1][0];
        const float* vT = &vS[kt & 1][0];
#pragma unroll 4
        for (int j = 0; j < 32; j++) {
            float2 vv = *reinterpret_cast<const float2*>(vT + j * 64 + tx * 2);
            float p0 = aT[(ty * 4 + 0) * 32 + j];
            float p1 = aT[(ty * 4 + 1) * 32 + j];
            float p2 = aT[(ty * 4 + 2) * 32 + j];
            float p3 = aT[(ty * 4 + 3) * 32 + j];
            o[0].x += p0 * vv.x; o[0].y += p0 * vv.y;
            o[1].x += p1 * vv.x; o[1].y += p1 * vv.y;
            o[2].x += p2 * vv.x; o[2].y += p2 * vv.y;
            o[3].x += p3 * vv.x; o[3].y += p3 * vv.y;
        }
        __syncthreads();
    }

#pragma unroll
    for (int r = 0; r < 4; r++) {
        float2* op = reinterpret_cast<float2*>(
            &out[((size_t)bh * LL + i0 + ty * 4 + r) * DD + tx * 2]);
        float2 cur = *op;
        cur.x += o[r].x; cur.y += o[r].y;
        *op = cur;
    }
}

// =====================================================================
extern "C" void kernel_launch(void* const* d_in, const int* in_sizes, int n_in,
                              void* d_out, int out_size)
{
    const float* q    = (const float*)d_in[0];
    const float* k    = (const float*)d_in[1];
    const float* v    = (const float*)d_in[2];
    const float* adjk = (const float*)d_in[3];
    const float* adjv = (const float*)d_in[4];
    const int*   mask = (const int*)d_in[5];
    float* out = (float*)d_out;

    int write_attn = (out_size >= OUT_ELEMS + ATTN_ELEMS) ? 1 : 0;
    float* attn_ext = out + OUT_ELEMS;

    cudaFuncSetAttribute(qk_kernel, cudaFuncAttributeMaxDynamicSharedMemorySize,
                         QK_SMEM_FLOATS * 4);
    cudaFuncSetAttribute(p1_kernel, cudaFuncAttributeMaxDynamicSharedMemorySize,
                         P1_SMEM_FLOATS * 4);

    qk_kernel<<<256, 256, QK_SMEM_FLOATS * 4>>>(q, k);
    p1_kernel<<<BB * (LL / P1_TI), P1_NT, P1_SMEM_FLOATS * 4>>>(
        q, adjk, mask, attn_ext, write_attn);
    adjv_kernel<<<BB * LL, 256>>>(adjv, out, attn_ext, write_attn);
    av_kernel<<<256, 256>>>(v, out, attn_ext, write_attn);
}